// round 14
// baseline (speedup 1.0000x reference)
#include <cuda_runtime.h>
#include <cuda_fp16.h>
#include <cstdint>

#define KDIM 4096
#define MDIM 4096   // B*S = 4*1024
#define NDIM 4096

// ---------------- device scratch (static allocation — allowed) ----------------
__device__ __half g_xh[(size_t)MDIM * KDIM];   // fp16(x) (11-bit mantissa)
__device__ __half g_wq[(size_t)NDIM * KDIM];   // q as fp16 (0..255 exact)
__device__ float  g_rowsum[MDIM];              // sum_k x[m,k]
__device__ float  g_errsum[MDIM];              // sum_k (x - fp16(x))[m,k]
__device__ float  g_cs[NDIM];                  // (sum_k q[n,k]) / K

// ---------------- fused prep: blocks 0..4095 -> x rows, 4096..8191 -> w rows ----------------
__global__ void prep_kernel(const float* __restrict__ x, const int* __restrict__ q)
{
    __shared__ float red[16];
    int tid = threadIdx.x;                            // 256 threads
    int wv = tid >> 5, ln = tid & 31;
    if (blockIdx.x < MDIM) {
        int m = blockIdx.x;
        const float4* xr = (const float4*)(x + (size_t)m * KDIM);
        uint2* hp = (uint2*)(g_xh + (size_t)m * KDIM);
        float s = 0.f, es = 0.f;
        #pragma unroll
        for (int i = 0; i < KDIM / 4 / 256; i++) {
            int idx = tid + i * 256;
            float4 v = xr[idx];
            s += (v.x + v.y) + (v.z + v.w);
            __half2 h01 = __floats2half2_rn(v.x, v.y);
            __half2 h23 = __floats2half2_rn(v.z, v.w);
            es += ((v.x - __low2float(h01)) + (v.y - __high2float(h01)))
                + ((v.z - __low2float(h23)) + (v.w - __high2float(h23)));
            uint2 o; o.x = *(uint32_t*)&h01; o.y = *(uint32_t*)&h23;
            hp[idx] = o;
        }
        #pragma unroll
        for (int o = 16; o > 0; o >>= 1) {
            s  += __shfl_xor_sync(0xffffffffu, s, o);
            es += __shfl_xor_sync(0xffffffffu, es, o);
        }
        if (ln == 0) { red[wv] = s; red[8 + wv] = es; }
        __syncthreads();
        if (tid == 0) {
            float a = 0.f, b = 0.f;
            #pragma unroll
            for (int i = 0; i < 8; i++) { a += red[i]; b += red[8 + i]; }
            g_rowsum[m] = a; g_errsum[m] = b;
        }
    } else {
        int n = blockIdx.x - MDIM;
        const int4* qr = (const int4*)(q + (size_t)n * KDIM);
        uint2* wp = (uint2*)(g_wq + (size_t)n * KDIM);
        int cs = 0;
        #pragma unroll
        for (int i = 0; i < KDIM / 4 / 256; i++) {
            int idx = tid + i * 256;
            int4 v = qr[idx];
            cs += (v.x + v.y) + (v.z + v.w);
            __half2 a = __floats2half2_rn((float)v.x, (float)v.y);
            __half2 b = __floats2half2_rn((float)v.z, (float)v.w);
            uint2 o; o.x = *(uint32_t*)&a; o.y = *(uint32_t*)&b;
            wp[idx] = o;
        }
        #pragma unroll
        for (int o = 16; o > 0; o >>= 1) cs += __shfl_xor_sync(0xffffffffu, cs, o);
        if (ln == 0) red[wv] = (float)cs;             // exact: <= 2^20
        __syncthreads();
        if (tid == 0) {
            float a = 0.f;
            #pragma unroll
            for (int i = 0; i < 8; i++) a += red[i];
            g_cs[n] = a * (1.f / KDIM);
        }
    }
}

// ---------------- GEMM config: 256x128 CTA, 512 thr (4x4 warps of 64x32), 1 CTA/SM ----------------
constexpr int BM = 256;
constexpr int BN = 128;
constexpr int BK = 64;                      // fp16 elems per k-tile = 128B data per row
constexpr int KT = KDIM / BK;               // 64
constexpr int STAGES = 3;
constexpr int PITCH = 144;                  // 128B data + 16B pad: 16B-chunk = 9r+c mod 32,
                                            // distinct mod 8 per ldmatrix phase -> conflict-free
constexpr int A_BYTES = BM * PITCH;         // 36864
constexpr int B_BYTES = BN * PITCH;         // 18432
constexpr int OFF_B = A_BYTES;
constexpr int STAGE_BYTES = A_BYTES + B_BYTES;      // 55296
constexpr int SMEM_TOTAL  = STAGES * STAGE_BYTES;   // 165888 (1 CTA/SM, 128 regs/thread)

// ---------------- PTX helpers (sm_80-portable only) ----------------
__device__ __forceinline__ uint32_t smem_u32(const void* p) {
    uint32_t a;
    asm("{ .reg .u64 t; cvta.to.shared.u64 t, %1; cvt.u32.u64 %0, t; }" : "=r"(a) : "l"(p));
    return a;
}
__device__ __forceinline__ void cp_async16(uint32_t s, const void* g) {
    asm volatile("cp.async.cg.shared.global [%0], [%1], 16;" :: "r"(s), "l"(g) : "memory");
}
__device__ __forceinline__ void cp_commit() { asm volatile("cp.async.commit_group;" ::: "memory"); }
template <int N> __device__ __forceinline__ void cp_wait() {
    asm volatile("cp.async.wait_group %0;" :: "n"(N) : "memory");
}
__device__ __forceinline__ void ldsm4(uint32_t* r, uint32_t addr) {
    asm volatile("ldmatrix.sync.aligned.m8n8.x4.shared.b16 {%0,%1,%2,%3}, [%4];"
                 : "=r"(r[0]), "=r"(r[1]), "=r"(r[2]), "=r"(r[3]) : "r"(addr));
}
__device__ __forceinline__ void mma16816(float* c, const uint32_t* a, uint32_t b0, uint32_t b1) {
    asm volatile("mma.sync.aligned.m16n8k16.row.col.f32.f16.f16.f32 "
                 "{%0,%1,%2,%3}, {%4,%5,%6,%7}, {%8,%9}, {%0,%1,%2,%3};"
                 : "+f"(c[0]), "+f"(c[1]), "+f"(c[2]), "+f"(c[3])
                 : "r"(a[0]), "r"(a[1]), "r"(a[2]), "r"(a[3]), "r"(b0), "r"(b1));
}

// ---------------- tile loads: 3072 x 16B chunks / 512 threads = 6 each ----------------
__device__ __forceinline__ void issue_tile(int tid, int tm, int tn, int kt, uint32_t sbase)
{
    // A: 256 rows x 8 chunks = 2048; 4 per thread
    #pragma unroll
    for (int i = 0; i < 4; i++) {
        int ch = tid + i * 512;
        int r = ch >> 3, c = ch & 7;
        cp_async16(sbase + (uint32_t)(r * PITCH + c * 16),
                   g_xh + (size_t)(tm * BM + r) * KDIM + (size_t)kt * BK + c * 8);
    }
    // B: 128 rows x 8 chunks = 1024; 2 per thread
    #pragma unroll
    for (int i = 0; i < 2; i++) {
        int ch = tid + i * 512;
        int r = ch >> 3, c = ch & 7;
        cp_async16(sbase + OFF_B + (uint32_t)(r * PITCH + c * 16),
                   g_wq + (size_t)(tn * BN + r) * KDIM + (size_t)kt * BK + c * 8);
    }
}

// ---------------- main GEMM: acc = h * q^T (fp32 accum), fused rank-1-corrected dequant ----------------
__global__ void __launch_bounds__(512, 1) gemm_kernel(
    float* __restrict__ out,
    const float* __restrict__ scales,
    const int*   __restrict__ zps,
    const float* __restrict__ bias)
{
    extern __shared__ __align__(128) uint8_t smem_buf[];
    const uint32_t smem_base = smem_u32(smem_buf);
    const int tid = threadIdx.x, wid = tid >> 5, lane = tid & 31;
    const int warp_m = wid & 3, warp_n = wid >> 2;          // 4 x 4 warps, 64 x 32 each
    const int lane16 = lane & 15, laneHi = lane >> 4;

    // L2-friendly rasterization: groups of 8 m-tiles, tile_m fastest
    constexpr int NTM = MDIM / BM, NTN = NDIM / BN, GROUP_M = 8;
    int pid = blockIdx.x;
    int nig = GROUP_M * NTN;
    int first_m = (pid / nig) * GROUP_M;
    int gsz = (NTM - first_m < GROUP_M) ? (NTM - first_m) : GROUP_M;
    int tile_m = first_m + (pid % gsz);
    int tile_n = (pid % nig) / gsz;

    const uint32_t offA = (uint32_t)((warp_m * 64 + lane16) * PITCH + laneHi * 16);
    const uint32_t offB = (uint32_t)(OFF_B + (warp_n * 32 + lane16) * PITCH + laneHi * 16);

    float acc[4][4][4];                                     // [mtile16][ntile8][frag] = 64 regs
    #pragma unroll
    for (int i = 0; i < 4; i++)
        #pragma unroll
        for (int j = 0; j < 4; j++)
            #pragma unroll
            for (int k = 0; k < 4; k++) acc[i][j][k] = 0.f;

    #pragma unroll
    for (int s = 0; s < STAGES - 1; s++) {                  // prefetch tiles 0,1
        issue_tile(tid, tile_m, tile_n, s, smem_base + s * STAGE_BYTES);
        cp_commit();
    }

    for (int kt = 0; kt < KT; kt++) {
        cp_wait<STAGES - 2>();                              // stage kt resident
        __syncthreads();                                    // all reads of kt-1 done

        int pf = kt + STAGES - 1;                           // refill (kt-1)%STAGES buffer
        if (pf < KT) issue_tile(tid, tile_m, tile_n, pf, smem_base + (pf % STAGES) * STAGE_BYTES);
        cp_commit();

        const uint32_t aAd = smem_base + (kt % STAGES) * STAGE_BYTES + offA;
        const uint32_t bAd = smem_base + (kt % STAGES) * STAGE_BYTES + offB;

        #pragma unroll
        for (int ks = 0; ks < 4; ks++) {                    // four K=16 steps per BK=64
            uint32_t ah[4][4], bb[2][4];
            #pragma unroll
            for (int mt = 0; mt < 4; mt++) ldsm4(ah[mt], aAd + mt * (16 * PITCH) + ks * 32);
            ldsm4(bb[0], bAd + ks * 32);
            ldsm4(bb[1], bAd + 16 * PITCH + ks * 32);
            #pragma unroll
            for (int mt = 0; mt < 4; mt++)
                #pragma unroll
                for (int p = 0; p < 2; p++) {
                    mma16816(acc[mt][2 * p],     ah[mt], bb[p][0], bb[p][2]);
                    mma16816(acc[mt][2 * p + 1], ah[mt], bb[p][1], bb[p][3]);
                }
        }
    }

    // ---------------- epilogue: Y = s*(acc + errsum*csbar - zp*rowsum) + b ----------------
    const int gr = lane >> 2, gc = lane & 3;
    #pragma unroll
    for (int mt = 0; mt < 4; mt++) {
        int r0 = tile_m * BM + warp_m * 64 + mt * 16 + gr;
        float rs0 = g_rowsum[r0],     es0 = g_errsum[r0];
        float rs1 = g_rowsum[r0 + 8], es1 = g_errsum[r0 + 8];
        float* o0 = out + (size_t)r0 * NDIM;
        float* o1 = o0 + (size_t)8 * NDIM;
        #pragma unroll
        for (int nt = 0; nt < 4; nt++) {
            int col = tile_n * BN + warp_n * 32 + nt * 8 + gc * 2;
            float2 sc = *(const float2*)(scales + col);
            int2   zp = *(const int2*)(zps + col);
            float2 bi = *(const float2*)(bias + col);
            float2 cs = *(const float2*)(g_cs + col);
            const float* a = acc[mt][nt];
            float2 v0, v1;
            v0.x = fmaf(sc.x, fmaf(es0, cs.x, a[0]) - (float)zp.x * rs0, bi.x);
            v0.y = fmaf(sc.y, fmaf(es0, cs.y, a[1]) - (float)zp.y * rs0, bi.y);
            v1.x = fmaf(sc.x, fmaf(es1, cs.x, a[2]) - (float)zp.x * rs1, bi.x);
            v1.y = fmaf(sc.y, fmaf(es1, cs.y, a[3]) - (float)zp.y * rs1, bi.y);
            *(float2*)(o0 + col) = v0;
            *(float2*)(o1 + col) = v1;
        }
    }
}

// ---------------- launch ----------------
extern "C" void kernel_launch(void* const* d_in, const int* in_sizes, int n_in,
                              void* d_out, int out_size)
{
    const float* x      = (const float*)d_in[0];
    const int*   qw     = (const int*)  d_in[1];
    const float* scales = (const float*)d_in[2];
    const int*   zps    = (const int*)  d_in[3];
    const float* bias   = (const float*)d_in[4];
    float* out = (float*)d_out;

    prep_kernel<<<MDIM + NDIM, 256>>>(x, qw);

    cudaFuncSetAttribute(gemm_kernel, cudaFuncAttributeMaxDynamicSharedMemorySize, SMEM_TOTAL);
    gemm_kernel<<<(MDIM / BM) * (NDIM / BN), 512, SMEM_TOTAL>>>(out, scales, zps, bias);
}

// round 16
// speedup vs baseline: 1.2000x; 1.2000x over previous
#include <cuda_runtime.h>
#include <cuda_fp16.h>
#include <cstdint>

#define KDIM 4096
#define MDIM 4096   // B*S = 4*1024
#define NDIM 4096

// ---------------- device scratch (static allocation — allowed) ----------------
__device__ __half g_xh[(size_t)MDIM * KDIM];   // fp16(x) (11-bit mantissa)
__device__ __half g_wq[(size_t)NDIM * KDIM];   // q as fp16 (0..255 exact)
__device__ float  g_rowsum[MDIM];              // sum_k x[m,k]
__device__ float  g_errsum[MDIM];              // sum_k (x - fp16(x))[m,k]
__device__ float  g_cs[NDIM];                  // (sum_k q[n,k]) / K

// ---------------- fused prep: blocks 0..4095 -> x rows, 4096..8191 -> w rows ----------------
__global__ void prep_kernel(const float* __restrict__ x, const int* __restrict__ q)
{
    __shared__ float red[16];
    int tid = threadIdx.x;                            // 256 threads
    int wv = tid >> 5, ln = tid & 31;
    if (blockIdx.x < MDIM) {
        int m = blockIdx.x;
        const float4* xr = (const float4*)(x + (size_t)m * KDIM);
        uint2* hp = (uint2*)(g_xh + (size_t)m * KDIM);
        float s = 0.f, es = 0.f;
        #pragma unroll
        for (int i = 0; i < KDIM / 4 / 256; i++) {
            int idx = tid + i * 256;
            float4 v = xr[idx];
            s += (v.x + v.y) + (v.z + v.w);
            __half2 h01 = __floats2half2_rn(v.x, v.y);
            __half2 h23 = __floats2half2_rn(v.z, v.w);
            es += ((v.x - __low2float(h01)) + (v.y - __high2float(h01)))
                + ((v.z - __low2float(h23)) + (v.w - __high2float(h23)));
            uint2 o; o.x = *(uint32_t*)&h01; o.y = *(uint32_t*)&h23;
            hp[idx] = o;
        }
        #pragma unroll
        for (int o = 16; o > 0; o >>= 1) {
            s  += __shfl_xor_sync(0xffffffffu, s, o);
            es += __shfl_xor_sync(0xffffffffu, es, o);
        }
        if (ln == 0) { red[wv] = s; red[8 + wv] = es; }
        __syncthreads();
        if (tid == 0) {
            float a = 0.f, b = 0.f;
            #pragma unroll
            for (int i = 0; i < 8; i++) { a += red[i]; b += red[8 + i]; }
            g_rowsum[m] = a; g_errsum[m] = b;
        }
    } else {
        int n = blockIdx.x - MDIM;
        const int4* qr = (const int4*)(q + (size_t)n * KDIM);
        uint2* wp = (uint2*)(g_wq + (size_t)n * KDIM);
        int cs = 0;
        #pragma unroll
        for (int i = 0; i < KDIM / 4 / 256; i++) {
            int idx = tid + i * 256;
            int4 v = qr[idx];
            cs += (v.x + v.y) + (v.z + v.w);
            __half2 a = __floats2half2_rn((float)v.x, (float)v.y);
            __half2 b = __floats2half2_rn((float)v.z, (float)v.w);
            uint2 o; o.x = *(uint32_t*)&a; o.y = *(uint32_t*)&b;
            wp[idx] = o;
        }
        #pragma unroll
        for (int o = 16; o > 0; o >>= 1) cs += __shfl_xor_sync(0xffffffffu, cs, o);
        if (ln == 0) red[wv] = (float)cs;             // exact: <= 2^20
        __syncthreads();
        if (tid == 0) {
            float a = 0.f;
            #pragma unroll
            for (int i = 0; i < 8; i++) a += red[i];
            g_cs[n] = a * (1.f / KDIM);
        }
    }
}

// ---------------- GEMM config: 128x128 CTA, 256 threads (2x4 warps of 64x32), 2 CTAs/SM ----------------
constexpr int BM = 128;
constexpr int BN = 128;
constexpr int BK = 64;                      // fp16 elems per k-tile = 128B data per row
constexpr int KT = KDIM / BK;               // 64
constexpr int STAGES = 3;
constexpr int PITCH = 144;                  // 128B data + 16B pad: 16B-chunk = 9r+c mod 32,
                                            // distinct mod 8 per ldmatrix phase -> conflict-free
constexpr int TILE_BYTES = BM * PITCH;      // 18432
constexpr int OFF_B = TILE_BYTES;
constexpr int STAGE_BYTES = 2 * TILE_BYTES; // 36864
constexpr int SMEM_TOTAL  = STAGES * STAGE_BYTES;   // 110592 (x2 CTAs = 221KB/SM)

// ---------------- PTX helpers (sm_80-portable only) ----------------
__device__ __forceinline__ uint32_t smem_u32(const void* p) {
    uint32_t a;
    asm("{ .reg .u64 t; cvta.to.shared.u64 t, %1; cvt.u32.u64 %0, t; }" : "=r"(a) : "l"(p));
    return a;
}
__device__ __forceinline__ void cp_async16(uint32_t s, const void* g) {
    asm volatile("cp.async.cg.shared.global [%0], [%1], 16;" :: "r"(s), "l"(g) : "memory");
}
__device__ __forceinline__ void cp_commit() { asm volatile("cp.async.commit_group;" ::: "memory"); }
template <int N> __device__ __forceinline__ void cp_wait() {
    asm volatile("cp.async.wait_group %0;" :: "n"(N) : "memory");
}
__device__ __forceinline__ void ldsm4(uint32_t* r, uint32_t addr) {
    asm volatile("ldmatrix.sync.aligned.m8n8.x4.shared.b16 {%0,%1,%2,%3}, [%4];"
                 : "=r"(r[0]), "=r"(r[1]), "=r"(r[2]), "=r"(r[3]) : "r"(addr));
}
__device__ __forceinline__ void mma16816(float* c, const uint32_t* a, uint32_t b0, uint32_t b1) {
    asm volatile("mma.sync.aligned.m16n8k16.row.col.f32.f16.f16.f32 "
                 "{%0,%1,%2,%3}, {%4,%5,%6,%7}, {%8,%9}, {%0,%1,%2,%3};"
                 : "+f"(c[0]), "+f"(c[1]), "+f"(c[2]), "+f"(c[3])
                 : "r"(a[0]), "r"(a[1]), "r"(a[2]), "r"(a[3]), "r"(b0), "r"(b1));
}

// ---------------- tile loads: 1024 x 16B chunks / 256 threads = 4 each ----------------
__device__ __forceinline__ void issue_tile(int tid, int tm, int tn, int kt, uint32_t sbase)
{
    // A: 128 rows x 8 chunks = 1024; wait: 128*8=1024 chunks? A has 8 chunks/row -> 1024; 4/thread
    #pragma unroll
    for (int i = 0; i < 2; i++) {
        int ch = tid + i * 256;
        int r = ch >> 2, c = ch & 3;                        // rows via 4-chunk split below
        (void)r; (void)c;
    }
    // A: 128 rows x 8 chunks = 1024 chunks; 4 per thread
    #pragma unroll
    for (int i = 0; i < 4; i++) {
        int ch = tid + i * 256;
        int r = ch >> 3, c = ch & 7;
        cp_async16(sbase + (uint32_t)(r * PITCH + c * 16),
                   g_xh + (size_t)(tm * BM + r) * KDIM + (size_t)kt * BK + c * 8);
    }
    // B: 128 rows x 8 chunks = 1024 chunks; 4 per thread
    #pragma unroll
    for (int i = 0; i < 4; i++) {
        int ch = tid + i * 256;
        int r = ch >> 3, c = ch & 7;
        cp_async16(sbase + OFF_B + (uint32_t)(r * PITCH + c * 16),
                   g_wq + (size_t)(tn * BN + r) * KDIM + (size_t)kt * BK + c * 8);
    }
}

// ---------------- main GEMM: acc = h * q^T (fp32 accum), fused rank-1-corrected dequant ----------------
__global__ void __launch_bounds__(256, 2) gemm_kernel(
    float* __restrict__ out,
    const float* __restrict__ scales,
    const int*   __restrict__ zps,
    const float* __restrict__ bias)
{
    extern __shared__ __align__(128) uint8_t smem_buf[];
    const uint32_t smem_base = smem_u32(smem_buf);
    const int tid = threadIdx.x, wid = tid >> 5, lane = tid & 31;
    const int warp_m = wid & 1, warp_n = wid >> 1;          // 2 x 4 warps, 64 x 32 each
    const int lane16 = lane & 15, laneHi = lane >> 4;

    // L2-friendly rasterization: groups of 8 m-tiles, tile_m fastest
    constexpr int NTM = MDIM / BM, NTN = NDIM / BN, GROUP_M = 8;
    int pid = blockIdx.x;
    int nig = GROUP_M * NTN;
    int first_m = (pid / nig) * GROUP_M;
    int gsz = (NTM - first_m < GROUP_M) ? (NTM - first_m) : GROUP_M;
    int tile_m = first_m + (pid % gsz);
    int tile_n = (pid % nig) / gsz;

    const uint32_t offA = (uint32_t)((warp_m * 64 + lane16) * PITCH + laneHi * 16);
    const uint32_t offB = (uint32_t)(OFF_B + (warp_n * 32 + lane16) * PITCH + laneHi * 16);

    float acc[4][4][4];                                     // [mtile16][ntile8][frag] = 64 regs
    #pragma unroll
    for (int i = 0; i < 4; i++)
        #pragma unroll
        for (int j = 0; j < 4; j++)
            #pragma unroll
            for (int k = 0; k < 4; k++) acc[i][j][k] = 0.f;

    #pragma unroll
    for (int s = 0; s < STAGES - 1; s++) {                  // prefetch tiles 0,1
        issue_tile(tid, tile_m, tile_n, s, smem_base + s * STAGE_BYTES);
        cp_commit();
    }

    for (int kt = 0; kt < KT; kt++) {
        cp_wait<STAGES - 2>();                              // stage kt resident
        __syncthreads();                                    // all reads of kt-1 done

        const uint32_t aAd = smem_base + (kt % STAGES) * STAGE_BYTES + offA;
        const uint32_t bAd = smem_base + (kt % STAGES) * STAGE_BYTES + offB;
        int pf = kt + STAGES - 1;                           // refill (kt-1)%STAGES buffer

        #pragma unroll
        for (int ks = 0; ks < 4; ks++) {                    // four K=16 steps per BK=64
            uint32_t ah[4][4], bb[2][4];
            ldsm4(bb[0], bAd + ks * 32);
            ldsm4(bb[1], bAd + 16 * PITCH + ks * 32);
            #pragma unroll
            for (int mt = 0; mt < 4; mt++) ldsm4(ah[mt], aAd + mt * (16 * PITCH) + ks * 32);
            if (ks == 0) {                                  // prefetch issue hidden behind ks=0 compute
                if (pf < KT) issue_tile(tid, tile_m, tile_n, pf, smem_base + (pf % STAGES) * STAGE_BYTES);
                cp_commit();
            }
            #pragma unroll
            for (int mt = 0; mt < 4; mt++)
                #pragma unroll
                for (int p = 0; p < 2; p++) {
                    mma16816(acc[mt][2 * p],     ah[mt], bb[p][0], bb[p][2]);
                    mma16816(acc[mt][2 * p + 1], ah[mt], bb[p][1], bb[p][3]);
                }
        }
    }

    // ---------------- epilogue: Y = s*(acc + errsum*csbar - zp*rowsum) + b ----------------
    const int gr = lane >> 2, gc = lane & 3;
    #pragma unroll
    for (int mt = 0; mt < 4; mt++) {
        int r0 = tile_m * BM + warp_m * 64 + mt * 16 + gr;
        float rs0 = g_rowsum[r0],     es0 = g_errsum[r0];
        float rs1 = g_rowsum[r0 + 8], es1 = g_errsum[r0 + 8];
        float* o0 = out + (size_t)r0 * NDIM;
        float* o1 = o0 + (size_t)8 * NDIM;
        #pragma unroll
        for (int nt = 0; nt < 4; nt++) {
            int col = tile_n * BN + warp_n * 32 + nt * 8 + gc * 2;
            float2 sc = *(const float2*)(scales + col);
            int2   zp = *(const int2*)(zps + col);
            float2 bi = *(const float2*)(bias + col);
            float2 cs = *(const float2*)(g_cs + col);
            const float* a = acc[mt][nt];
            float2 v0, v1;
            v0.x = fmaf(sc.x, fmaf(es0, cs.x, a[0]) - (float)zp.x * rs0, bi.x);
            v0.y = fmaf(sc.y, fmaf(es0, cs.y, a[1]) - (float)zp.y * rs0, bi.y);
            v1.x = fmaf(sc.x, fmaf(es1, cs.x, a[2]) - (float)zp.x * rs1, bi.x);
            v1.y = fmaf(sc.y, fmaf(es1, cs.y, a[3]) - (float)zp.y * rs1, bi.y);
            *(float2*)(o0 + col) = v0;
            *(float2*)(o1 + col) = v1;
        }
    }
}

// ---------------- launch ----------------
extern "C" void kernel_launch(void* const* d_in, const int* in_sizes, int n_in,
                              void* d_out, int out_size)
{
    const float* x      = (const float*)d_in[0];
    const int*   qw     = (const int*)  d_in[1];
    const float* scales = (const float*)d_in[2];
    const int*   zps    = (const int*)  d_in[3];
    const float* bias   = (const float*)d_in[4];
    float* out = (float*)d_out;

    prep_kernel<<<MDIM + NDIM, 256>>>(x, qw);

    cudaFuncSetAttribute(gemm_kernel, cudaFuncAttributeMaxDynamicSharedMemorySize, SMEM_TOTAL);
    gemm_kernel<<<(MDIM / BM) * (NDIM / BN), 256, SMEM_TOTAL>>>(out, scales, zps, bias);
}